// round 2
// baseline (speedup 1.0000x reference)
#include <cuda_runtime.h>
#include <math.h>

// Problem dims
#define T_  128
#define B_  64
#define V_  8192
#define H_  2048
#define VH_ 10240   // V_ + H_

// State history for all timesteps: g_states[t][b][h]  (64 MB, device global = allowed scratch)
__device__ float g_states[(size_t)T_ * B_ * H_];
// Never written -> stays zero (initial state)
__device__ float g_zero_state[B_ * H_];

// ---------------------------------------------------------------------------
// Recurrence step: new_state[b,h] = tanh( hidden_b[h] + hidden_w[h, tok[b]]
//                                        + sum_k prev[b,k] * hidden_w[h, V_+k] )
// GEMM M=64(b) x N=2048(h) x K=2048. grid = H_/16 = 128 blocks, 128 threads.
// Each thread computes 4 b x 2 h.
// ---------------------------------------------------------------------------
__global__ void rnn_step_kernel(int t,
                                const int* __restrict__ tok_all,       // [T_][B_] int32
                                const float* __restrict__ hidden_w,    // [H_][VH_]
                                const float* __restrict__ hidden_b)    // [H_]
{
    const float* prev = (t == 0) ? g_zero_state : (g_states + (size_t)(t - 1) * B_ * H_);
    float*       next = g_states + (size_t)t * B_ * H_;
    const int*   tok  = tok_all + (size_t)t * B_;

    __shared__ float As[16][64];   // [k][b]
    __shared__ float Bs[16][16];   // [k][h]

    const int tid = threadIdx.x;
    const int h0  = blockIdx.x * 16;
    const int hp  = (tid & 7) * 2;    // local h pair base
    const int bg  = (tid >> 3) * 4;   // local b quad base

    float acc[4][2];
#pragma unroll
    for (int i = 0; i < 4; i++)
#pragma unroll
        for (int j = 0; j < 2; j++) acc[i][j] = 0.0f;

    // loader indices
    const int a_b  = tid & 63;
    const int a_kq = (tid >> 6) * 8;       // 0 or 8
    const int b_h  = tid & 15;
    const int b_kq = (tid >> 4) * 2;       // 0,2,...,14

    for (int k0 = 0; k0 < H_; k0 += 16) {
        // A tile: 64 x 16 (transposed into smem)
        {
            const float* p = prev + (size_t)a_b * H_ + k0 + a_kq;
            float4 v0 = *(const float4*)(p);
            float4 v1 = *(const float4*)(p + 4);
            As[a_kq + 0][a_b] = v0.x; As[a_kq + 1][a_b] = v0.y;
            As[a_kq + 2][a_b] = v0.z; As[a_kq + 3][a_b] = v0.w;
            As[a_kq + 4][a_b] = v1.x; As[a_kq + 5][a_b] = v1.y;
            As[a_kq + 6][a_b] = v1.z; As[a_kq + 7][a_b] = v1.w;
        }
        // B tile: 16 h rows x 16 k from the recurrent block of hidden_w
        {
            const float* wr = hidden_w + (size_t)(h0 + b_h) * VH_ + V_ + k0 + b_kq;
            Bs[b_kq + 0][b_h] = wr[0];
            Bs[b_kq + 1][b_h] = wr[1];
        }
        __syncthreads();
#pragma unroll
        for (int kk = 0; kk < 16; kk++) {
            float4 a  = *(const float4*)&As[kk][bg];
            float  w0 = Bs[kk][hp + 0];
            float  w1 = Bs[kk][hp + 1];
            acc[0][0] += a.x * w0; acc[0][1] += a.x * w1;
            acc[1][0] += a.y * w0; acc[1][1] += a.y * w1;
            acc[2][0] += a.z * w0; acc[2][1] += a.z * w1;
            acc[3][0] += a.w * w0; acc[3][1] += a.w * w1;
        }
        __syncthreads();
    }

    // epilogue: + bias + one-hot embedding column, tanh
#pragma unroll
    for (int j = 0; j < 2; j++) {
        const int   h    = h0 + hp + j;
        const float bias = hidden_b[h];
#pragma unroll
        for (int i = 0; i < 4; i++) {
            const int b  = bg + i;
            int       tk = tok[b];
            // Defensive clamp: if token dtype assumption is ever wrong we get a
            // rel_err signal instead of an illegal memory access.
            tk = (tk < 0) ? 0 : ((tk >= V_) ? (V_ - 1) : tk);
            float pre = acc[i][j] + bias + hidden_w[(size_t)h * VH_ + (size_t)tk];
            next[(size_t)b * H_ + h] = tanhf(pre);
        }
    }
}

// ---------------------------------------------------------------------------
// Batched output projection:
//   out[m, v] = output_b[v] + sum_h S[m,h] * output_w[v,h]
// with S = g_states viewed as [T_*B_][H_] (row m = (t,b)).
// Classic SGEMM: BM=BN=128, BK=8, 256 threads, 8x8 microtile.
// grid = (V_/128, (T_*B_)/128) = (64, 64)
// ---------------------------------------------------------------------------
__global__ void out_gemm_kernel(const float* __restrict__ W,   // [V_][H_]
                                const float* __restrict__ ob,  // [V_]
                                float* __restrict__ out)       // [T_*B_][V_]
{
    __shared__ float As[8][128];  // [k][m]
    __shared__ float Bs[8][128];  // [k][n]

    const float* S = g_states;    // [T_*B_][H_]

    const int tid = threadIdx.x;
    const int m0  = blockIdx.y * 128;
    const int n0  = blockIdx.x * 128;
    const int tx  = tid & 15;
    const int ty  = tid >> 4;
    const int mr  = ty * 8;
    const int nr  = tx * 8;

    float acc[8][8];
#pragma unroll
    for (int i = 0; i < 8; i++)
#pragma unroll
        for (int j = 0; j < 8; j++) acc[i][j] = 0.0f;

    const int lrow = tid >> 1;        // 0..127
    const int lk   = (tid & 1) * 4;   // 0 or 4

    for (int k0 = 0; k0 < H_; k0 += 8) {
        float4 av = *(const float4*)(S + (size_t)(m0 + lrow) * H_ + k0 + lk);
        float4 bv = *(const float4*)(W + (size_t)(n0 + lrow) * H_ + k0 + lk);
        As[lk + 0][lrow] = av.x; As[lk + 1][lrow] = av.y;
        As[lk + 2][lrow] = av.z; As[lk + 3][lrow] = av.w;
        Bs[lk + 0][lrow] = bv.x; Bs[lk + 1][lrow] = bv.y;
        Bs[lk + 2][lrow] = bv.z; Bs[lk + 3][lrow] = bv.w;
        __syncthreads();
#pragma unroll
        for (int kk = 0; kk < 8; kk++) {
            float a[8], b[8];
            *(float4*)&a[0] = *(const float4*)&As[kk][mr];
            *(float4*)&a[4] = *(const float4*)&As[kk][mr + 4];
            *(float4*)&b[0] = *(const float4*)&Bs[kk][nr];
            *(float4*)&b[4] = *(const float4*)&Bs[kk][nr + 4];
#pragma unroll
            for (int i = 0; i < 8; i++)
#pragma unroll
                for (int j = 0; j < 8; j++)
                    acc[i][j] += a[i] * b[j];
        }
        __syncthreads();
    }

#pragma unroll
    for (int i = 0; i < 8; i++) {
        const int m = m0 + mr + i;
#pragma unroll
        for (int j = 0; j < 8; j += 4) {
            const int n = n0 + nr + j;
            float4 o;
            o.x = acc[i][j + 0] + ob[n + 0];
            o.y = acc[i][j + 1] + ob[n + 1];
            o.z = acc[i][j + 2] + ob[n + 2];
            o.w = acc[i][j + 3] + ob[n + 3];
            *(float4*)(out + (size_t)m * V_ + n) = o;
        }
    }
}

// Copy final state (g_states[T_-1]) to the tail of the output buffer.
__global__ void copy_final_state_kernel(float* __restrict__ dst)
{
    const float* src = g_states + (size_t)(T_ - 1) * B_ * H_;
    int idx = blockIdx.x * blockDim.x + threadIdx.x;
    if (idx < B_ * H_) dst[idx] = src[idx];
}

extern "C" void kernel_launch(void* const* d_in, const int* in_sizes, int n_in,
                              void* d_out, int out_size)
{
    const int*   inputs   = (const int*)d_in[0];     // [T_][B_] int32 (JAX x64 disabled)
    const float* hidden_w = (const float*)d_in[1];   // [H_][VH_]
    const float* hidden_b = (const float*)d_in[2];   // [H_]
    const float* output_w = (const float*)d_in[3];   // [V_][H_]
    const float* output_b = (const float*)d_in[4];   // [V_]
    float*       out      = (float*)d_out;

    (void)in_sizes; (void)n_in;

    // Sequential recurrence: 128 dependent launches (graph nodes)
    for (int t = 0; t < T_; t++) {
        rnn_step_kernel<<<H_ / 16, 128>>>(t, inputs, hidden_w, hidden_b);
    }

    // Batched output projection over all timesteps
    dim3 grid(V_ / 128, (T_ * B_) / 128);
    out_gemm_kernel<<<grid, 256>>>(output_w, output_b, out);

    // Final state, if the output buffer includes it (outputs first, then final_state)
    const size_t outputs_elems = (size_t)T_ * B_ * V_;
    if ((size_t)out_size >= outputs_elems + (size_t)B_ * H_) {
        copy_final_state_kernel<<<(B_ * H_ + 255) / 256, 256>>>(out + outputs_elems);
    }
}

// round 7
// speedup vs baseline: 1.2612x; 1.2612x over previous
#include <cuda_runtime.h>
#include <math.h>

// Problem dims
#define T_  128
#define B_  64
#define V_  8192
#define H_  2048
#define VH_ 10240   // V_ + H_

#define NCTA 128          // persistent CTAs, one per SM (h-slice of 16)
#define TPB  256
#define HW   16           // h rows per CTA
#define BK   128          // k chunk staged per double-buffer slot
#define WS_STRIDE 2052    // 2048 + 4 pad (keeps 16B align, spreads banks)
#define AS_STRIDE 132     // 128 + 4 pad (16B-aligned rows)

// State history: g_states[t][b][h]  (64 MB device-global scratch)
__device__ __align__(16) float g_states[(size_t)T_ * B_ * H_];

// Grid barrier state (zero-initialized)
__device__ unsigned g_bar_gen;
__device__ unsigned g_bar_cnt;

// ---------------------------------------------------------------------------
// helpers
// ---------------------------------------------------------------------------
__device__ __forceinline__ void ffma2(unsigned long long& d,
                                      unsigned long long a,
                                      unsigned long long b)
{
    asm("fma.rn.f32x2 %0, %1, %2, %0;" : "+l"(d) : "l"(a), "l"(b));
}

__device__ __forceinline__ float f2_lo(unsigned long long v)
{ return __int_as_float((int)(unsigned)(v & 0xffffffffu)); }
__device__ __forceinline__ float f2_hi(unsigned long long v)
{ return __int_as_float((int)(unsigned)(v >> 32)); }

__device__ __forceinline__ void cp_async16(void* sdst, const void* gsrc)
{
    unsigned sa = (unsigned)__cvta_generic_to_shared(sdst);
    asm volatile("cp.async.cg.shared.global [%0], [%1], 16;\n" :: "r"(sa), "l"(gsrc));
}
__device__ __forceinline__ void cp_commit()
{ asm volatile("cp.async.commit_group;\n"); }
template<int N> __device__ __forceinline__ void cp_wait()
{ asm volatile("cp.async.wait_group %0;\n" :: "n"(N)); }

__device__ __forceinline__ void grid_barrier()
{
    __syncthreads();
    if (threadIdx.x == 0) {
        __threadfence();
        unsigned gen = *(volatile unsigned*)&g_bar_gen;
        unsigned t = atomicAdd(&g_bar_cnt, 1u);
        if (t == NCTA - 1) {
            atomicExch(&g_bar_cnt, 0u);
            __threadfence();
            atomicAdd(&g_bar_gen, 1u);
        } else {
            while (*(volatile unsigned*)&g_bar_gen == gen) { }
        }
        __threadfence();
    }
    __syncthreads();
}

// ---------------------------------------------------------------------------
// Persistent recurrence kernel.
// grid = 128 CTAs x 256 threads. CTA owns h rows [bid*16, bid*16+16).
// W_hh slice (16 x 2048) lives in SMEM for all 128 steps.
// Per step: new[b,h] = tanh( bias[h] + W[h, tok[b]] + sum_k prev[b,k]*W[h,V+k] )
// ---------------------------------------------------------------------------
extern __shared__ float s_mem[];

__global__ __launch_bounds__(TPB, 1)
void rnn_persistent(const int* __restrict__ tok_all,     // [T_][B_]
                    const float* __restrict__ hidden_w,  // [H_][VH_]
                    const float* __restrict__ hidden_b)  // [H_]
{
    float* ws   = s_mem;                    // [16][WS_STRIDE]
    float* abuf = s_mem + HW * WS_STRIDE;   // 2 x [64][AS_STRIDE]

    const int tid = threadIdx.x;
    const int h0  = blockIdx.x * HW;

    // --- preload W_hh slice into smem (once) ---
    for (int r = 0; r < HW; ++r) {
        const float* src = hidden_w + (size_t)(h0 + r) * VH_ + V_;
        float*       dst = ws + r * WS_STRIDE;
        for (int idx = tid; idx < H_ / 4; idx += TPB)
            *(float4*)(dst + idx * 4) = *(const float4*)(src + idx * 4);
    }
    __syncthreads();

    // compute-thread mapping: 2 b x 2 h per thread
    const int hh = (tid & 7) * 2;        // 0..14 (CTA-local h)
    const int bb = (tid >> 3) * 2;       // 0..62
    // staging mapping: 64 rows x 32 float4 cols
    const int st_c4 = tid & 31;          // float4 column
    const int st_r0 = tid >> 5;          // 0..7 (rows r0 + 8i)

    const int hA = h0 + hh, hB = hA + 1;
    const float biasA = hidden_b[hA];
    const float biasB = hidden_b[hB];
    const float* wrowA = hidden_w + (size_t)hA * VH_;
    const float* wrowB = hidden_w + (size_t)hB * VH_;

    for (int t = 0; t < T_; ++t) {
        unsigned long long acc00 = 0ull, acc01 = 0ull, acc10 = 0ull, acc11 = 0ull;

        if (t > 0) {
            const float* prev = g_states + (size_t)(t - 1) * B_ * H_;

            // prefetch chunk 0 into buffer 0
            {
                float* buf = abuf;
                const int k0 = 0;
#pragma unroll
                for (int i = 0; i < 8; ++i) {
                    int r = st_r0 + 8 * i;
                    cp_async16(buf + r * AS_STRIDE + st_c4 * 4,
                               prev + (size_t)r * H_ + k0 + st_c4 * 4);
                }
                cp_commit();
            }

            const int NCH = H_ / BK;   // 16
            for (int c = 0; c < NCH; ++c) {
                if (c + 1 < NCH) {
                    float* buf = abuf + ((c + 1) & 1) * (64 * AS_STRIDE);
                    const int k0 = (c + 1) * BK;
#pragma unroll
                    for (int i = 0; i < 8; ++i) {
                        int r = st_r0 + 8 * i;
                        cp_async16(buf + r * AS_STRIDE + st_c4 * 4,
                                   prev + (size_t)r * H_ + k0 + st_c4 * 4);
                    }
                    cp_commit();
                    cp_wait<1>();
                } else {
                    cp_wait<0>();
                }
                __syncthreads();

                const float* buf = abuf + (c & 1) * (64 * AS_STRIDE);
                const float* A0 = buf + bb * AS_STRIDE;
                const float* A1 = A0 + AS_STRIDE;
                const float* W0 = ws + hh * WS_STRIDE + c * BK;
                const float* W1 = W0 + WS_STRIDE;
#pragma unroll 8
                for (int kk = 0; kk < BK; kk += 4) {
                    ulonglong2 a0 = *(const ulonglong2*)(A0 + kk);
                    ulonglong2 a1 = *(const ulonglong2*)(A1 + kk);
                    ulonglong2 w0 = *(const ulonglong2*)(W0 + kk);
                    ulonglong2 w1 = *(const ulonglong2*)(W1 + kk);
                    ffma2(acc00, a0.x, w0.x); ffma2(acc00, a0.y, w0.y);
                    ffma2(acc01, a0.x, w1.x); ffma2(acc01, a0.y, w1.y);
                    ffma2(acc10, a1.x, w0.x); ffma2(acc10, a1.y, w0.y);
                    ffma2(acc11, a1.x, w1.x); ffma2(acc11, a1.y, w1.y);
                }
                __syncthreads();
            }
        }

        // --- epilogue: bias + one-hot embedding + tanh, write state[t] ---
        {
            float* next = g_states + (size_t)t * B_ * H_;
            int tkA = tok_all[t * B_ + bb];
            int tkB = tok_all[t * B_ + bb + 1];
            tkA = (tkA < 0) ? 0 : ((tkA >= V_) ? V_ - 1 : tkA);
            tkB = (tkB < 0) ? 0 : ((tkB >= V_) ? V_ - 1 : tkB);
            float eA_bA = wrowA[tkA];   // h=hA, b=bb
            float eB_bA = wrowB[tkA];   // h=hB, b=bb
            float eA_bB = wrowA[tkB];   // h=hA, b=bb+1
            float eB_bB = wrowB[tkB];   // h=hB, b=bb+1

            float s00 = f2_lo(acc00) + f2_hi(acc00);
            float s01 = f2_lo(acc01) + f2_hi(acc01);
            float s10 = f2_lo(acc10) + f2_hi(acc10);
            float s11 = f2_lo(acc11) + f2_hi(acc11);

            float2 vA, vB;
            vA.x = tanhf(s00 + biasA + eA_bA);
            vA.y = tanhf(s01 + biasB + eB_bA);
            vB.x = tanhf(s10 + biasA + eA_bB);
            vB.y = tanhf(s11 + biasB + eB_bB);

            // FIX (R6 bug): store at global h index (h0 + hh), not local hh.
            *(float2*)(next + (size_t)bb * H_ + h0 + hh)       = vA;
            *(float2*)(next + (size_t)(bb + 1) * H_ + h0 + hh) = vB;
        }

        grid_barrier();
    }
}

// ---------------------------------------------------------------------------
// Batched output projection with f32x2-packed FMAs:
//   out[m, v] = output_b[v] + sum_h S[m,h] * output_w[v,h]
// BM=BN=128, BK=8, 256 threads, 8m x 8n microtile (as 8m x 4 n-pairs).
// A is staged DUPLICATED ({v,v}) so a-operand f32x2 needs no packing movs.
// ---------------------------------------------------------------------------
__global__ void out_gemm_kernel(const float* __restrict__ W,   // [V_][H_]
                                const float* __restrict__ ob,  // [V_]
                                float* __restrict__ out)       // [T_*B_][V_]
{
    __shared__ float AsD[8][258];   // [k][2*m] duplicated pairs (+pad)
    __shared__ float Bs[8][128];    // [k][n]

    const float* S = g_states;      // [T_*B_][H_]

    const int tid = threadIdx.x;
    const int m0  = blockIdx.y * 128;
    const int n0  = blockIdx.x * 128;
    const int tx  = tid & 15;
    const int ty  = tid >> 4;
    const int mr  = ty * 8;
    const int nr  = tx * 8;

    unsigned long long acc[8][4];
#pragma unroll
    for (int i = 0; i < 8; i++)
#pragma unroll
        for (int j = 0; j < 4; j++) acc[i][j] = 0ull;

    const int lrow = tid >> 1;        // 0..127
    const int lk   = (tid & 1) * 4;   // 0 or 4

    for (int k0 = 0; k0 < H_; k0 += 8) {
        float4 av = *(const float4*)(S + (size_t)(m0 + lrow) * H_ + k0 + lk);
        float4 bv = *(const float4*)(W + (size_t)(n0 + lrow) * H_ + k0 + lk);
        *(float2*)&AsD[lk + 0][2 * lrow] = make_float2(av.x, av.x);
        *(float2*)&AsD[lk + 1][2 * lrow] = make_float2(av.y, av.y);
        *(float2*)&AsD[lk + 2][2 * lrow] = make_float2(av.z, av.z);
        *(float2*)&AsD[lk + 3][2 * lrow] = make_float2(av.w, av.w);
        Bs[lk + 0][lrow] = bv.x; Bs[lk + 1][lrow] = bv.y;
        Bs[lk + 2][lrow] = bv.z; Bs[lk + 3][lrow] = bv.w;
        __syncthreads();
#pragma unroll
        for (int kk = 0; kk < 8; kk++) {
            ulonglong2 b01 = *(const ulonglong2*)&Bs[kk][nr];
            ulonglong2 b23 = *(const ulonglong2*)&Bs[kk][nr + 4];
#pragma unroll
            for (int i = 0; i < 8; i++) {
                unsigned long long a2 = *(const unsigned long long*)&AsD[kk][2 * (mr + i)];
                ffma2(acc[i][0], a2, b01.x);
                ffma2(acc[i][1], a2, b01.y);
                ffma2(acc[i][2], a2, b23.x);
                ffma2(acc[i][3], a2, b23.y);
            }
        }
        __syncthreads();
    }

#pragma unroll
    for (int i = 0; i < 8; i++) {
        const int m = m0 + mr + i;
        const int n = n0 + nr;
        float4 o0, o1;
        o0.x = f2_lo(acc[i][0]) + ob[n + 0];
        o0.y = f2_hi(acc[i][0]) + ob[n + 1];
        o0.z = f2_lo(acc[i][1]) + ob[n + 2];
        o0.w = f2_hi(acc[i][1]) + ob[n + 3];
        o1.x = f2_lo(acc[i][2]) + ob[n + 4];
        o1.y = f2_hi(acc[i][2]) + ob[n + 5];
        o1.z = f2_lo(acc[i][3]) + ob[n + 6];
        o1.w = f2_hi(acc[i][3]) + ob[n + 7];
        *(float4*)(out + (size_t)m * V_ + n)     = o0;
        *(float4*)(out + (size_t)m * V_ + n + 4) = o1;
    }
}

// Copy final state (g_states[T_-1]) to the tail of the output buffer.
__global__ void copy_final_state_kernel(float* __restrict__ dst)
{
    const float* src = g_states + (size_t)(T_ - 1) * B_ * H_;
    int idx = blockIdx.x * blockDim.x + threadIdx.x;
    if (idx < B_ * H_) dst[idx] = src[idx];
}

extern "C" void kernel_launch(void* const* d_in, const int* in_sizes, int n_in,
                              void* d_out, int out_size)
{
    const int*   inputs   = (const int*)d_in[0];     // [T_][B_] int32
    const float* hidden_w = (const float*)d_in[1];   // [H_][VH_]
    const float* hidden_b = (const float*)d_in[2];   // [H_]
    const float* output_w = (const float*)d_in[3];   // [V_][H_]
    const float* output_b = (const float*)d_in[4];   // [V_]
    float*       out      = (float*)d_out;

    (void)in_sizes; (void)n_in;

    const int smem_bytes = (HW * WS_STRIDE + 2 * 64 * AS_STRIDE) * sizeof(float);
    cudaFuncSetAttribute(rnn_persistent,
                         cudaFuncAttributeMaxDynamicSharedMemorySize, smem_bytes);

    // One persistent launch runs all 128 recurrence steps.
    rnn_persistent<<<NCTA, TPB, smem_bytes>>>(inputs, hidden_w, hidden_b);

    // Batched output projection over all timesteps
    dim3 grid(V_ / 128, (T_ * B_) / 128);
    out_gemm_kernel<<<grid, 256>>>(output_w, output_b, out);

    // Final state, if the output buffer includes it (outputs first, then final_state)
    const size_t outputs_elems = (size_t)T_ * B_ * V_;
    if ((size_t)out_size >= outputs_elems + (size_t)B_ * H_) {
        copy_final_state_kernel<<<(B_ * H_ + 255) / 256, 256>>>(out + outputs_elems);
    }
}

// round 8
// speedup vs baseline: 1.3957x; 1.1066x over previous
#include <cuda_runtime.h>
#include <math.h>

// Problem dims
#define T_  128
#define B_  64
#define V_  8192
#define H_  2048
#define VH_ 10240   // V_ + H_

#define NCTA 128          // persistent CTAs, one per SM (h-slice of 16)
#define TPB  256
#define HW   16           // h rows per CTA
#define BK   128          // k chunk staged per double-buffer slot
#define WS_STRIDE 2052    // 2048 + 4 pad
#define AS_STRIDE 132     // 128 + 4 pad

// State history: g_states[t][b][h]  (64 MB device-global scratch)
__device__ __align__(16) float g_states[(size_t)T_ * B_ * H_];

// Grid barrier state (zero-initialized)
__device__ unsigned g_bar_gen;
__device__ unsigned g_bar_cnt;

// ---------------------------------------------------------------------------
// helpers
// ---------------------------------------------------------------------------
__device__ __forceinline__ void ffma2(unsigned long long& d,
                                      unsigned long long a,
                                      unsigned long long b)
{
    asm("fma.rn.f32x2 %0, %1, %2, %0;" : "+l"(d) : "l"(a), "l"(b));
}

__device__ __forceinline__ float f2_lo(unsigned long long v)
{ return __int_as_float((int)(unsigned)(v & 0xffffffffu)); }
__device__ __forceinline__ float f2_hi(unsigned long long v)
{ return __int_as_float((int)(unsigned)(v >> 32)); }

__device__ __forceinline__ void cp_async16(void* sdst, const void* gsrc)
{
    unsigned sa = (unsigned)__cvta_generic_to_shared(sdst);
    asm volatile("cp.async.cg.shared.global [%0], [%1], 16;\n" :: "r"(sa), "l"(gsrc));
}
__device__ __forceinline__ void cp_commit()
{ asm volatile("cp.async.commit_group;\n"); }
template<int N> __device__ __forceinline__ void cp_wait()
{ asm volatile("cp.async.wait_group %0;\n" :: "n"(N)); }

__device__ __forceinline__ void grid_barrier()
{
    __syncthreads();
    if (threadIdx.x == 0) {
        __threadfence();
        unsigned gen = *(volatile unsigned*)&g_bar_gen;
        unsigned t = atomicAdd(&g_bar_cnt, 1u);
        if (t == NCTA - 1) {
            atomicExch(&g_bar_cnt, 0u);
            __threadfence();
            atomicAdd(&g_bar_gen, 1u);
        } else {
            while (*(volatile unsigned*)&g_bar_gen == gen) { }
        }
        __threadfence();
    }
    __syncthreads();
}

// ---------------------------------------------------------------------------
// Persistent recurrence kernel (unchanged from R7 — the experiment's control).
// ---------------------------------------------------------------------------
extern __shared__ float s_mem[];

__global__ __launch_bounds__(TPB, 1)
void rnn_persistent(const int* __restrict__ tok_all,     // [T_][B_]
                    const float* __restrict__ hidden_w,  // [H_][VH_]
                    const float* __restrict__ hidden_b)  // [H_]
{
    float* ws   = s_mem;                    // [16][WS_STRIDE]
    float* abuf = s_mem + HW * WS_STRIDE;   // 2 x [64][AS_STRIDE]

    const int tid = threadIdx.x;
    const int h0  = blockIdx.x * HW;

    // preload W_hh slice into smem (once)
    for (int r = 0; r < HW; ++r) {
        const float* src = hidden_w + (size_t)(h0 + r) * VH_ + V_;
        float*       dst = ws + r * WS_STRIDE;
        for (int idx = tid; idx < H_ / 4; idx += TPB)
            *(float4*)(dst + idx * 4) = *(const float4*)(src + idx * 4);
    }
    __syncthreads();

    const int hh = (tid & 7) * 2;        // 0..14 (CTA-local h)
    const int bb = (tid >> 3) * 2;       // 0..62
    const int st_c4 = tid & 31;
    const int st_r0 = tid >> 5;

    const int hA = h0 + hh, hB = hA + 1;
    const float biasA = hidden_b[hA];
    const float biasB = hidden_b[hB];
    const float* wrowA = hidden_w + (size_t)hA * VH_;
    const float* wrowB = hidden_w + (size_t)hB * VH_;

    for (int t = 0; t < T_; ++t) {
        unsigned long long acc00 = 0ull, acc01 = 0ull, acc10 = 0ull, acc11 = 0ull;

        if (t > 0) {
            const float* prev = g_states + (size_t)(t - 1) * B_ * H_;

            {
                float* buf = abuf;
#pragma unroll
                for (int i = 0; i < 8; ++i) {
                    int r = st_r0 + 8 * i;
                    cp_async16(buf + r * AS_STRIDE + st_c4 * 4,
                               prev + (size_t)r * H_ + st_c4 * 4);
                }
                cp_commit();
            }

            const int NCH = H_ / BK;   // 16
            for (int c = 0; c < NCH; ++c) {
                if (c + 1 < NCH) {
                    float* buf = abuf + ((c + 1) & 1) * (64 * AS_STRIDE);
                    const int k0 = (c + 1) * BK;
#pragma unroll
                    for (int i = 0; i < 8; ++i) {
                        int r = st_r0 + 8 * i;
                        cp_async16(buf + r * AS_STRIDE + st_c4 * 4,
                                   prev + (size_t)r * H_ + k0 + st_c4 * 4);
                    }
                    cp_commit();
                    cp_wait<1>();
                } else {
                    cp_wait<0>();
                }
                __syncthreads();

                const float* buf = abuf + (c & 1) * (64 * AS_STRIDE);
                const float* A0 = buf + bb * AS_STRIDE;
                const float* A1 = A0 + AS_STRIDE;
                const float* W0 = ws + hh * WS_STRIDE + c * BK;
                const float* W1 = W0 + WS_STRIDE;
#pragma unroll 8
                for (int kk = 0; kk < BK; kk += 4) {
                    ulonglong2 a0 = *(const ulonglong2*)(A0 + kk);
                    ulonglong2 a1 = *(const ulonglong2*)(A1 + kk);
                    ulonglong2 w0 = *(const ulonglong2*)(W0 + kk);
                    ulonglong2 w1 = *(const ulonglong2*)(W1 + kk);
                    ffma2(acc00, a0.x, w0.x); ffma2(acc00, a0.y, w0.y);
                    ffma2(acc01, a0.x, w1.x); ffma2(acc01, a0.y, w1.y);
                    ffma2(acc10, a1.x, w0.x); ffma2(acc10, a1.y, w0.y);
                    ffma2(acc11, a1.x, w1.x); ffma2(acc11, a1.y, w1.y);
                }
                __syncthreads();
            }
        }

        // epilogue: bias + one-hot embedding + tanh, write state[t]
        {
            float* next = g_states + (size_t)t * B_ * H_;
            int tkA = tok_all[t * B_ + bb];
            int tkB = tok_all[t * B_ + bb + 1];
            tkA = (tkA < 0) ? 0 : ((tkA >= V_) ? V_ - 1 : tkA);
            tkB = (tkB < 0) ? 0 : ((tkB >= V_) ? V_ - 1 : tkB);
            float eA_bA = wrowA[tkA];
            float eB_bA = wrowB[tkA];
            float eA_bB = wrowA[tkB];
            float eB_bB = wrowB[tkB];

            float s00 = f2_lo(acc00) + f2_hi(acc00);
            float s01 = f2_lo(acc01) + f2_hi(acc01);
            float s10 = f2_lo(acc10) + f2_hi(acc10);
            float s11 = f2_lo(acc11) + f2_hi(acc11);

            float2 vA, vB;
            vA.x = tanhf(s00 + biasA + eA_bA);
            vA.y = tanhf(s01 + biasB + eB_bA);
            vB.x = tanhf(s10 + biasA + eA_bB);
            vB.y = tanhf(s11 + biasB + eB_bB);

            *(float2*)(next + (size_t)bb * H_ + h0 + hh)       = vA;
            *(float2*)(next + (size_t)(bb + 1) * H_ + h0 + hh) = vB;
        }

        grid_barrier();
    }
}

// ---------------------------------------------------------------------------
// Batched output projection — R2 SCALAR version (measured-good), reverted from
// the FFMA2 experiment to disambiguate where R7's missing time went.
//   out[m, v] = output_b[v] + sum_h S[m,h] * output_w[v,h]
// BM=BN=128, BK=8, 256 threads, 8x8 microtile.
// ---------------------------------------------------------------------------
__global__ void out_gemm_kernel(const float* __restrict__ W,   // [V_][H_]
                                const float* __restrict__ ob,  // [V_]
                                float* __restrict__ out)       // [T_*B_][V_]
{
    __shared__ float As[8][128];  // [k][m]
    __shared__ float Bs[8][128];  // [k][n]

    const float* S = g_states;    // [T_*B_][H_]

    const int tid = threadIdx.x;
    const int m0  = blockIdx.y * 128;
    const int n0  = blockIdx.x * 128;
    const int tx  = tid & 15;
    const int ty  = tid >> 4;
    const int mr  = ty * 8;
    const int nr  = tx * 8;

    float acc[8][8];
#pragma unroll
    for (int i = 0; i < 8; i++)
#pragma unroll
        for (int j = 0; j < 8; j++) acc[i][j] = 0.0f;

    const int lrow = tid >> 1;        // 0..127
    const int lk   = (tid & 1) * 4;   // 0 or 4

    for (int k0 = 0; k0 < H_; k0 += 8) {
        float4 av = *(const float4*)(S + (size_t)(m0 + lrow) * H_ + k0 + lk);
        float4 bv = *(const float4*)(W + (size_t)(n0 + lrow) * H_ + k0 + lk);
        As[lk + 0][lrow] = av.x; As[lk + 1][lrow] = av.y;
        As[lk + 2][lrow] = av.z; As[lk + 3][lrow] = av.w;
        Bs[lk + 0][lrow] = bv.x; Bs[lk + 1][lrow] = bv.y;
        Bs[lk + 2][lrow] = bv.z; Bs[lk + 3][lrow] = bv.w;
        __syncthreads();
#pragma unroll
        for (int kk = 0; kk < 8; kk++) {
            float a[8], b[8];
            *(float4*)&a[0] = *(const float4*)&As[kk][mr];
            *(float4*)&a[4] = *(const float4*)&As[kk][mr + 4];
            *(float4*)&b[0] = *(const float4*)&Bs[kk][nr];
            *(float4*)&b[4] = *(const float4*)&Bs[kk][nr + 4];
#pragma unroll
            for (int i = 0; i < 8; i++)
#pragma unroll
                for (int j = 0; j < 8; j++)
                    acc[i][j] += a[i] * b[j];
        }
        __syncthreads();
    }

#pragma unroll
    for (int i = 0; i < 8; i++) {
        const int m = m0 + mr + i;
#pragma unroll
        for (int j = 0; j < 8; j += 4) {
            const int n = n0 + nr + j;
            float4 o;
            o.x = acc[i][j + 0] + ob[n + 0];
            o.y = acc[i][j + 1] + ob[n + 1];
            o.z = acc[i][j + 2] + ob[n + 2];
            o.w = acc[i][j + 3] + ob[n + 3];
            *(float4*)(out + (size_t)m * V_ + n) = o;
        }
    }
}

// Copy final state (g_states[T_-1]) to the tail of the output buffer.
__global__ void copy_final_state_kernel(float* __restrict__ dst)
{
    const float* src = g_states + (size_t)(T_ - 1) * B_ * H_;
    int idx = blockIdx.x * blockDim.x + threadIdx.x;
    if (idx < B_ * H_) dst[idx] = src[idx];
}

extern "C" void kernel_launch(void* const* d_in, const int* in_sizes, int n_in,
                              void* d_out, int out_size)
{
    const int*   inputs   = (const int*)d_in[0];     // [T_][B_] int32
    const float* hidden_w = (const float*)d_in[1];   // [H_][VH_]
    const float* hidden_b = (const float*)d_in[2];   // [H_]
    const float* output_w = (const float*)d_in[3];   // [V_][H_]
    const float* output_b = (const float*)d_in[4];   // [V_]
    float*       out      = (float*)d_out;

    (void)in_sizes; (void)n_in;

    const int smem_bytes = (HW * WS_STRIDE + 2 * 64 * AS_STRIDE) * sizeof(float);
    cudaFuncSetAttribute(rnn_persistent,
                         cudaFuncAttributeMaxDynamicSharedMemorySize, smem_bytes);

    // One persistent launch runs all 128 recurrence steps.
    rnn_persistent<<<NCTA, TPB, smem_bytes>>>(inputs, hidden_w, hidden_b);

    // Batched output projection over all timesteps
    dim3 grid(V_ / 128, (T_ * B_) / 128);
    out_gemm_kernel<<<grid, 256>>>(output_w, output_b, out);

    // Final state, if the output buffer includes it (outputs first, then final_state)
    const size_t outputs_elems = (size_t)T_ * B_ * V_;
    if ((size_t)out_size >= outputs_elems + (size_t)B_ * H_) {
        copy_final_state_kernel<<<(B_ * H_ + 255) / 256, 256>>>(out + outputs_elems);
    }
}

// round 9
// speedup vs baseline: 1.8014x; 1.2907x over previous
#include <cuda_runtime.h>
#include <math.h>

// Problem dims
#define T_  128
#define B_  64
#define V_  8192
#define H_  2048
#define VH_ 10240   // V_ + H_

#define NCTA 128          // persistent CTAs, one per SM (h-slice of 16)
#define TPB  256
#define HW   16           // h rows per CTA
#define BK   128          // k chunk staged per double-buffer slot
#define WS_STRIDE 2052    // 2048 + 4 pad (16B-aligned rows)
#define AS_STRIDE 132     // 128 + 4 pad (16B-aligned rows)

// State history: g_states[t][b][h]  (64 MB device-global scratch)
__device__ __align__(16) float g_states[(size_t)T_ * B_ * H_];

// Grid barrier state (zero-initialized)
__device__ unsigned g_bar_gen;
__device__ unsigned g_bar_cnt;

// ---------------------------------------------------------------------------
// helpers
// ---------------------------------------------------------------------------
__device__ __forceinline__ void ffma2(unsigned long long& d,
                                      unsigned long long a,
                                      unsigned long long b)
{
    asm("fma.rn.f32x2 %0, %1, %2, %0;" : "+l"(d) : "l"(a), "l"(b));
}

__device__ __forceinline__ float f2_lo(unsigned long long v)
{ return __int_as_float((int)(unsigned)(v & 0xffffffffu)); }
__device__ __forceinline__ float f2_hi(unsigned long long v)
{ return __int_as_float((int)(unsigned)(v >> 32)); }

__device__ __forceinline__ void cp_async16(void* sdst, const void* gsrc)
{
    unsigned sa = (unsigned)__cvta_generic_to_shared(sdst);
    asm volatile("cp.async.cg.shared.global [%0], [%1], 16;\n" :: "r"(sa), "l"(gsrc));
}
__device__ __forceinline__ void cp_commit()
{ asm volatile("cp.async.commit_group;\n"); }
template<int N> __device__ __forceinline__ void cp_wait()
{ asm volatile("cp.async.wait_group %0;\n" :: "n"(N)); }

__device__ __forceinline__ void grid_barrier()
{
    __syncthreads();
    if (threadIdx.x == 0) {
        __threadfence();
        unsigned gen = *(volatile unsigned*)&g_bar_gen;
        unsigned t = atomicAdd(&g_bar_cnt, 1u);
        if (t == NCTA - 1) {
            atomicExch(&g_bar_cnt, 0u);
            __threadfence();
            atomicAdd(&g_bar_gen, 1u);
        } else {
            while (*(volatile unsigned*)&g_bar_gen == gen) { }
        }
        __threadfence();
    }
    __syncthreads();
}

// ---------------------------------------------------------------------------
// Persistent recurrence kernel, v2: 4b x 4h register tile, 4-way k-split.
// grid = 128 CTAs x 256 threads. CTA owns h rows [bid*16, bid*16+16).
// Thread mapping: ks = tid&3 (k split), hq = (tid>>2)&3 (h quad),
//                 bq = tid>>4 (b quad).  k interleave: 16 floats/iter,
//                 this thread takes floats [it*16 + ks*4, +4).
// ---------------------------------------------------------------------------
extern __shared__ float s_mem[];

__global__ __launch_bounds__(TPB, 1)
void rnn_persistent(const int* __restrict__ tok_all,     // [T_][B_]
                    const float* __restrict__ hidden_w,  // [H_][VH_]
                    const float* __restrict__ hidden_b)  // [H_]
{
    float* ws   = s_mem;                    // [16][WS_STRIDE]
    float* abuf = s_mem + HW * WS_STRIDE;   // 2 x [64][AS_STRIDE]

    const int tid = threadIdx.x;
    const int h0  = blockIdx.x * HW;

    // preload W_hh slice into smem (once)
    for (int r = 0; r < HW; ++r) {
        const float* src = hidden_w + (size_t)(h0 + r) * VH_ + V_;
        float*       dst = ws + r * WS_STRIDE;
        for (int idx = tid; idx < H_ / 4; idx += TPB)
            *(float4*)(dst + idx * 4) = *(const float4*)(src + idx * 4);
    }
    __syncthreads();

    // compute mapping
    const int ks = tid & 3;
    const int hq = (tid >> 2) & 3;
    const int bq = tid >> 4;            // 0..15
    const bool writer = (ks == 0);

    // staging mapping: 64 rows x 32 float4 cols
    const int st_c4 = tid & 31;
    const int st_r0 = tid >> 5;

    // biases for this thread's 4 h values (h0 + hq*4 .. +3)
    const float4 bias4 = *(const float4*)(hidden_b + h0 + hq * 4);
    // embedding row pointers
    const float* wrow0 = hidden_w + (size_t)(h0 + hq * 4 + 0) * VH_;
    const float* wrow1 = hidden_w + (size_t)(h0 + hq * 4 + 1) * VH_;
    const float* wrow2 = hidden_w + (size_t)(h0 + hq * 4 + 2) * VH_;
    const float* wrow3 = hidden_w + (size_t)(h0 + hq * 4 + 3) * VH_;

    for (int t = 0; t < T_; ++t) {
        unsigned long long acc[4][4];
#pragma unroll
        for (int bi = 0; bi < 4; ++bi)
#pragma unroll
            for (int hj = 0; hj < 4; ++hj) acc[bi][hj] = 0ull;

        if (t > 0) {
            const float* prev = g_states + (size_t)(t - 1) * B_ * H_;

            // prefetch chunk 0 into buffer 0
            {
                float* buf = abuf;
#pragma unroll
                for (int i = 0; i < 8; ++i) {
                    int r = st_r0 + 8 * i;
                    cp_async16(buf + r * AS_STRIDE + st_c4 * 4,
                               prev + (size_t)r * H_ + st_c4 * 4);
                }
                cp_commit();
            }

            const int NCH = H_ / BK;   // 16
            for (int c = 0; c < NCH; ++c) {
                if (c + 1 < NCH) {
                    float* buf = abuf + ((c + 1) & 1) * (64 * AS_STRIDE);
                    const int k0 = (c + 1) * BK;
#pragma unroll
                    for (int i = 0; i < 8; ++i) {
                        int r = st_r0 + 8 * i;
                        cp_async16(buf + r * AS_STRIDE + st_c4 * 4,
                                   prev + (size_t)r * H_ + k0 + st_c4 * 4);
                    }
                    cp_commit();
                    cp_wait<1>();
                } else {
                    cp_wait<0>();
                }
                __syncthreads();

                const float* buf = abuf + (c & 1) * (64 * AS_STRIDE);
                const float* Abase = buf + (bq * 4) * AS_STRIDE + ks * 4;
                const float* Wbase = ws + (hq * 4) * WS_STRIDE + c * BK + ks * 4;

#pragma unroll
                for (int it = 0; it < 8; ++it) {
                    const int ko = it * 16;
                    ulonglong2 a0 = *(const ulonglong2*)(Abase + 0 * AS_STRIDE + ko);
                    ulonglong2 a1 = *(const ulonglong2*)(Abase + 1 * AS_STRIDE + ko);
                    ulonglong2 a2 = *(const ulonglong2*)(Abase + 2 * AS_STRIDE + ko);
                    ulonglong2 a3 = *(const ulonglong2*)(Abase + 3 * AS_STRIDE + ko);
                    ulonglong2 w0 = *(const ulonglong2*)(Wbase + 0 * WS_STRIDE + ko);
                    ulonglong2 w1 = *(const ulonglong2*)(Wbase + 1 * WS_STRIDE + ko);
                    ulonglong2 w2 = *(const ulonglong2*)(Wbase + 2 * WS_STRIDE + ko);
                    ulonglong2 w3 = *(const ulonglong2*)(Wbase + 3 * WS_STRIDE + ko);

                    ffma2(acc[0][0], a0.x, w0.x); ffma2(acc[0][0], a0.y, w0.y);
                    ffma2(acc[0][1], a0.x, w1.x); ffma2(acc[0][1], a0.y, w1.y);
                    ffma2(acc[0][2], a0.x, w2.x); ffma2(acc[0][2], a0.y, w2.y);
                    ffma2(acc[0][3], a0.x, w3.x); ffma2(acc[0][3], a0.y, w3.y);
                    ffma2(acc[1][0], a1.x, w0.x); ffma2(acc[1][0], a1.y, w0.y);
                    ffma2(acc[1][1], a1.x, w1.x); ffma2(acc[1][1], a1.y, w1.y);
                    ffma2(acc[1][2], a1.x, w2.x); ffma2(acc[1][2], a1.y, w2.y);
                    ffma2(acc[1][3], a1.x, w3.x); ffma2(acc[1][3], a1.y, w3.y);
                    ffma2(acc[2][0], a2.x, w0.x); ffma2(acc[2][0], a2.y, w0.y);
                    ffma2(acc[2][1], a2.x, w1.x); ffma2(acc[2][1], a2.y, w1.y);
                    ffma2(acc[2][2], a2.x, w2.x); ffma2(acc[2][2], a2.y, w2.y);
                    ffma2(acc[2][3], a2.x, w3.x); ffma2(acc[2][3], a2.y, w3.y);
                    ffma2(acc[3][0], a3.x, w0.x); ffma2(acc[3][0], a3.y, w0.y);
                    ffma2(acc[3][1], a3.x, w1.x); ffma2(acc[3][1], a3.y, w1.y);
                    ffma2(acc[3][2], a3.x, w2.x); ffma2(acc[3][2], a3.y, w2.y);
                    ffma2(acc[3][3], a3.x, w3.x); ffma2(acc[3][3], a3.y, w3.y);
                }
                __syncthreads();
            }
        }

        // reduce over ks lanes (4 consecutive lanes) and write
        float res[4][4];
#pragma unroll
        for (int bi = 0; bi < 4; ++bi) {
#pragma unroll
            for (int hj = 0; hj < 4; ++hj) {
                float s = f2_lo(acc[bi][hj]) + f2_hi(acc[bi][hj]);
                s += __shfl_xor_sync(0xffffffffu, s, 1);
                s += __shfl_xor_sync(0xffffffffu, s, 2);
                res[bi][hj] = s;
            }
        }

        if (writer) {
            float* next = g_states + (size_t)t * B_ * H_;
#pragma unroll
            for (int bi = 0; bi < 4; ++bi) {
                const int b = bq * 4 + bi;
                int tk = tok_all[t * B_ + b];
                tk = (tk < 0) ? 0 : ((tk >= V_) ? V_ - 1 : tk);
                float4 v;
                v.x = tanhf(res[bi][0] + bias4.x + wrow0[tk]);
                v.y = tanhf(res[bi][1] + bias4.y + wrow1[tk]);
                v.z = tanhf(res[bi][2] + bias4.z + wrow2[tk]);
                v.w = tanhf(res[bi][3] + bias4.w + wrow3[tk]);
                *(float4*)(next + (size_t)b * H_ + h0 + hq * 4) = v;
            }
        }

        grid_barrier();
    }
}

// ---------------------------------------------------------------------------
// Batched output projection (R2 scalar version, measured-good):
//   out[m, v] = output_b[v] + sum_h S[m,h] * output_w[v,h]
// BM=BN=128, BK=8, 256 threads, 8x8 microtile.
// ---------------------------------------------------------------------------
__global__ void out_gemm_kernel(const float* __restrict__ W,   // [V_][H_]
                                const float* __restrict__ ob,  // [V_]
                                float* __restrict__ out)       // [T_*B_][V_]
{
    __shared__ float As[8][128];  // [k][m]
    __shared__ float Bs[8][128];  // [k][n]

    const float* S = g_states;    // [T_*B_][H_]

    const int tid = threadIdx.x;
    const int m0  = blockIdx.y * 128;
    const int n0  = blockIdx.x * 128;
    const int tx  = tid & 15;
    const int ty  = tid >> 4;
    const int mr  = ty * 8;
    const int nr  = tx * 8;

    float acc[8][8];
#pragma unroll
    for (int i = 0; i < 8; i++)
#pragma unroll
        for (int j = 0; j < 8; j++) acc[i][j] = 0.0f;

    const int lrow = tid >> 1;        // 0..127
    const int lk   = (tid & 1) * 4;   // 0 or 4

    for (int k0 = 0; k0 < H_; k0 += 8) {
        float4 av = *(const float4*)(S + (size_t)(m0 + lrow) * H_ + k0 + lk);
        float4 bv = *(const float4*)(W + (size_t)(n0 + lrow) * H_ + k0 + lk);
        As[lk + 0][lrow] = av.x; As[lk + 1][lrow] = av.y;
        As[lk + 2][lrow] = av.z; As[lk + 3][lrow] = av.w;
        Bs[lk + 0][lrow] = bv.x; Bs[lk + 1][lrow] = bv.y;
        Bs[lk + 2][lrow] = bv.z; Bs[lk + 3][lrow] = bv.w;
        __syncthreads();
#pragma unroll
        for (int kk = 0; kk < 8; kk++) {
            float a[8], b[8];
            *(float4*)&a[0] = *(const float4*)&As[kk][mr];
            *(float4*)&a[4] = *(const float4*)&As[kk][mr + 4];
            *(float4*)&b[0] = *(const float4*)&Bs[kk][nr];
            *(float4*)&b[4] = *(const float4*)&Bs[kk][nr + 4];
#pragma unroll
            for (int i = 0; i < 8; i++)
#pragma unroll
                for (int j = 0; j < 8; j++)
                    acc[i][j] += a[i] * b[j];
        }
        __syncthreads();
    }

#pragma unroll
    for (int i = 0; i < 8; i++) {
        const int m = m0 + mr + i;
#pragma unroll
        for (int j = 0; j < 8; j += 4) {
            const int n = n0 + nr + j;
            float4 o;
            o.x = acc[i][j + 0] + ob[n + 0];
            o.y = acc[i][j + 1] + ob[n + 1];
            o.z = acc[i][j + 2] + ob[n + 2];
            o.w = acc[i][j + 3] + ob[n + 3];
            *(float4*)(out + (size_t)m * V_ + n) = o;
        }
    }
}

// Copy final state (g_states[T_-1]) to the tail of the output buffer.
__global__ void copy_final_state_kernel(float* __restrict__ dst)
{
    const float* src = g_states + (size_t)(T_ - 1) * B_ * H_;
    int idx = blockIdx.x * blockDim.x + threadIdx.x;
    if (idx < B_ * H_) dst[idx] = src[idx];
}

extern "C" void kernel_launch(void* const* d_in, const int* in_sizes, int n_in,
                              void* d_out, int out_size)
{
    const int*   inputs   = (const int*)d_in[0];     // [T_][B_] int32
    const float* hidden_w = (const float*)d_in[1];   // [H_][VH_]
    const float* hidden_b = (const float*)d_in[2];   // [H_]
    const float* output_w = (const float*)d_in[3];   // [V_][H_]
    const float* output_b = (const float*)d_in[4];   // [V_]
    float*       out      = (float*)d_out;

    (void)in_sizes; (void)n_in;

    const int smem_bytes = (HW * WS_STRIDE + 2 * 64 * AS_STRIDE) * sizeof(float);
    cudaFuncSetAttribute(rnn_persistent,
                         cudaFuncAttributeMaxDynamicSharedMemorySize, smem_bytes);

    // One persistent launch runs all 128 recurrence steps.
    rnn_persistent<<<NCTA, TPB, smem_bytes>>>(inputs, hidden_w, hidden_b);

    // Batched output projection over all timesteps
    dim3 grid(V_ / 128, (T_ * B_) / 128);
    out_gemm_kernel<<<grid, 256>>>(output_w, output_b, out);

    // Final state, if the output buffer includes it (outputs first, then final_state)
    const size_t outputs_elems = (size_t)T_ * B_ * V_;
    if ((size_t)out_size >= outputs_elems + (size_t)B_ * H_) {
        copy_final_state_kernel<<<(B_ * H_ + 255) / 256, 256>>>(out + outputs_elems);
    }
}